// round 8
// baseline (speedup 1.0000x reference)
#include <cuda_runtime.h>

// MVGeometricProduct — occupancy round: force 5 blocks/SM (regs<=51) via launch_bounds.
// R7 baseline: 64 regs -> hard 4-block RF cap -> 41.9% occ, issue 50.1%, 18.37us.
// Everything else identical to R7 (tail-amortized grid, MLP-8 loads, pad-21 smem).

#define NR 256
#define PADW 21
#define MINB 5

__device__ __forceinline__ void normalize8(const float* ww,
                                           float s0, float s1, float s2, float s3,
                                           float* wn) {
    float nrm0 = fabsf(ww[0]);
    float nrm1 = __fsqrt_rn(ww[1]*ww[1] + ww[2]*ww[2] + ww[3]*ww[3]);
    float nrm2 = __fsqrt_rn(ww[4]*ww[4] + ww[5]*ww[5] + ww[6]*ww[6]);
    float nrm3 = fabsf(ww[7]);
    float r0 = __fdividef(1.0f, fmaf(s0, nrm0 - 1.0f, 1.0f));
    float r1 = __fdividef(1.0f, fmaf(s1, nrm1 - 1.0f, 1.0f));
    float r2 = __fdividef(1.0f, fmaf(s2, nrm2 - 1.0f, 1.0f));
    float r3 = __fdividef(1.0f, fmaf(s3, nrm3 - 1.0f, 1.0f));
    wn[0] = ww[0] * r0;
    wn[1] = ww[1] * r1;  wn[2] = ww[2] * r1;  wn[3] = ww[3] * r1;
    wn[4] = ww[4] * r2;  wn[5] = ww[5] * r2;  wn[6] = ww[6] * r2;
    wn[7] = ww[7] * r3;
}

__device__ __forceinline__ void site_compute(const float* vi, const float* wn,
                                             const float* wt, float* o) {
#pragma unroll
    for (int t = 0; t < 8; ++t) o[t] = 0.0f;
#define T(I, K, J, S, P) o[J] = fmaf((S) * wt[P] * vi[I], wn[K], o[J]);
    // i = 0 (scalar)
    T(0,0,0, 1.f, 0)  T(0,1,1, 1.f, 1)  T(0,2,2, 1.f, 1)  T(0,3,3, 1.f, 1)
    T(0,4,4, 1.f, 2)  T(0,5,5, 1.f, 2)  T(0,6,6, 1.f, 2)  T(0,7,7, 1.f, 3)
    // i = 1 (e1)
    T(1,0,1, 1.f, 5)  T(1,1,0, 1.f, 4)  T(1,2,4, 1.f, 7)  T(1,3,5, 1.f, 7)
    T(1,4,2, 1.f, 6)  T(1,5,3, 1.f, 6)  T(1,6,7, 1.f, 9)  T(1,7,6, 1.f, 8)
    // i = 2 (e2)
    T(2,0,2, 1.f, 5)  T(2,1,4,-1.f, 7)  T(2,2,0, 1.f, 4)  T(2,3,6, 1.f, 7)
    T(2,4,1,-1.f, 6)  T(2,5,7,-1.f, 9)  T(2,6,3, 1.f, 6)  T(2,7,5,-1.f, 8)
    // i = 3 (e3)
    T(3,0,3, 1.f, 5)  T(3,1,5,-1.f, 7)  T(3,2,6,-1.f, 7)  T(3,3,0, 1.f, 4)
    T(3,4,7, 1.f, 9)  T(3,5,1,-1.f, 6)  T(3,6,2,-1.f, 6)  T(3,7,4, 1.f, 8)
    // i = 4 (e12)
    T(4,0,4,-1.f,13)  T(4,1,2, 1.f,11)  T(4,2,1,-1.f,11)  T(4,3,7,-1.f,15)
    T(4,4,0, 1.f,10)  T(4,5,6, 1.f,14)  T(4,6,5,-1.f,14)  T(4,7,3, 1.f,12)
    // i = 5 (e13)
    T(5,0,5,-1.f,13)  T(5,1,3, 1.f,11)  T(5,2,7, 1.f,15)  T(5,3,1,-1.f,11)
    T(5,4,6,-1.f,14)  T(5,5,0, 1.f,10)  T(5,6,4, 1.f,14)  T(5,7,2,-1.f,12)
    // i = 6 (e23)
    T(6,0,6,-1.f,13)  T(6,1,7,-1.f,15)  T(6,2,3, 1.f,11)  T(6,3,2,-1.f,11)
    T(6,4,5, 1.f,14)  T(6,5,4,-1.f,14)  T(6,6,0, 1.f,10)  T(6,7,1, 1.f,12)
    // i = 7 (e123)
    T(7,0,7,-1.f,19)  T(7,1,6,-1.f,18)  T(7,2,5, 1.f,18)  T(7,3,4,-1.f,18)
    T(7,4,3, 1.f,17)  T(7,5,2,-1.f,17)  T(7,6,1, 1.f,17)  T(7,7,0, 1.f,16)
#undef T
}

__global__ __launch_bounds__(NR, MINB) void mv_gp_kernel(
    const float* __restrict__ v,
    const float* __restrict__ w,
    const float* __restrict__ weight,
    const float* __restrict__ a,
    float* __restrict__ out,
    int B, int F)
{
    __shared__ float wt_s[NR * PADW];   // row-major, padded (gcd(21,32)=1)

    const int tid = threadIdx.x;
    const int n0  = blockIdx.x * NR;

    // ---- stage weight rows: coalesced float4 reads, scalar padded writes ----
    {
        const float4* wsrc = (const float4*)(weight + (size_t)n0 * 20);
#pragma unroll
        for (int it = 0; it < 5; ++it) {
            int i = tid + it * NR;          // 1280 float4 total
            float4 x = wsrc[i];
            int e = i * 4;
            int base = (e / 20) * PADW + (e % 20);
            wt_s[base + 0] = x.x;
            wt_s[base + 1] = x.y;
            wt_s[base + 2] = x.z;
            wt_s[base + 3] = x.w;
        }
    }

    const int n = n0 + tid;

    // sigmoid(a[n]) — coalesced float4 per thread
    const float4 a4 = *(const float4*)(a + (size_t)n * 4);
    const float s0 = __fdividef(1.0f, 1.0f + __expf(-a4.x));
    const float s1 = __fdividef(1.0f, 1.0f + __expf(-a4.y));
    const float s2 = __fdividef(1.0f, 1.0f + __expf(-a4.z));
    const float s3 = __fdividef(1.0f, 1.0f + __expf(-a4.w));

    __syncthreads();

    // per-thread weight row from smem (conflict-free: stride 21)
    float wt[20];
    const float* wrow = &wt_s[tid * PADW];
#pragma unroll
    for (int p = 0; p < 20; ++p) wt[p] = wrow[p];

    // ---- two batch rows per thread; all 8 LDG.128 before compute ----
    const int b0 = blockIdx.y * 2;
    const size_t siteA = (size_t)b0 * F + n;
    const size_t siteB = (b0 + 1 < B) ? siteA + (size_t)F : siteA;

    const float4* vA4 = (const float4*)(v + siteA * 8);
    const float4* wA4 = (const float4*)(w + siteA * 8);
    const float4* vB4 = (const float4*)(v + siteB * 8);
    const float4* wB4 = (const float4*)(w + siteB * 8);

    float4 va0 = vA4[0], va1 = vA4[1];
    float4 wa0 = wA4[0], wa1 = wA4[1];
    float4 vb0 = vB4[0], vb1 = vB4[1];
    float4 wb0 = wB4[0], wb1 = wB4[1];

    // ---- site A ----
    {
        float vi[8] = {va0.x, va0.y, va0.z, va0.w, va1.x, va1.y, va1.z, va1.w};
        float ww[8] = {wa0.x, wa0.y, wa0.z, wa0.w, wa1.x, wa1.y, wa1.z, wa1.w};
        float wn[8], o[8];
        normalize8(ww, s0, s1, s2, s3, wn);
        site_compute(vi, wn, wt, o);
        float4* o4 = (float4*)(out + siteA * 8);
        o4[0] = make_float4(o[0], o[1], o[2], o[3]);
        o4[1] = make_float4(o[4], o[5], o[6], o[7]);
    }
    // ---- site B ----
    {
        float vi[8] = {vb0.x, vb0.y, vb0.z, vb0.w, vb1.x, vb1.y, vb1.z, vb1.w};
        float ww[8] = {wb0.x, wb0.y, wb0.z, wb0.w, wb1.x, wb1.y, wb1.z, wb1.w};
        float wn[8], o[8];
        normalize8(ww, s0, s1, s2, s3, wn);
        site_compute(vi, wn, wt, o);
        float4* o4 = (float4*)(out + siteB * 8);
        o4[0] = make_float4(o[0], o[1], o[2], o[3]);
        o4[1] = make_float4(o[4], o[5], o[6], o[7]);
    }
}

extern "C" void kernel_launch(void* const* d_in, const int* in_sizes, int n_in,
                              void* d_out, int out_size) {
    const float* v      = (const float*)d_in[0];
    const float* w      = (const float*)d_in[1];
    const float* weight = (const float*)d_in[2];
    const float* a      = (const float*)d_in[3];
    float* out = (float*)d_out;

    int F     = in_sizes[3] / 4;        // a is [F, 4]
    int total = in_sizes[0] / 8;        // B * F
    int B     = total / F;

    dim3 grid(F / NR, (B + 1) / 2);
    mv_gp_kernel<<<grid, NR>>>(v, w, weight, a, out, B, F);
}

// round 10
// speedup vs baseline: 1.3971x; 1.3971x over previous
#include <cuda_runtime.h>

// MVGeometricProduct — persistent b-loop round (re-submit; prior run infra-failed).
// R7 (18.4us): 51 LSU-ops/thread of staging overhead over only 2 sites; LSU/issue-count bound.
// Now: grid = (3, ~196) ≈ one full wave at 4 blocks/SM; each block strides
// over b-pairs, so staging + wt regs + sigmoid amortize over ~5 b-pairs/thread.
// __launch_bounds__(256,4) pins the 64-reg regime (R8 showed 5-block squeeze spills).

#define NR 256
#define PADW 21

__device__ __forceinline__ void normalize8(const float* ww,
                                           float s0, float s1, float s2, float s3,
                                           float* wn) {
    float nrm0 = fabsf(ww[0]);
    float nrm1 = __fsqrt_rn(ww[1]*ww[1] + ww[2]*ww[2] + ww[3]*ww[3]);
    float nrm2 = __fsqrt_rn(ww[4]*ww[4] + ww[5]*ww[5] + ww[6]*ww[6]);
    float nrm3 = fabsf(ww[7]);
    float r0 = __fdividef(1.0f, fmaf(s0, nrm0 - 1.0f, 1.0f));
    float r1 = __fdividef(1.0f, fmaf(s1, nrm1 - 1.0f, 1.0f));
    float r2 = __fdividef(1.0f, fmaf(s2, nrm2 - 1.0f, 1.0f));
    float r3 = __fdividef(1.0f, fmaf(s3, nrm3 - 1.0f, 1.0f));
    wn[0] = ww[0] * r0;
    wn[1] = ww[1] * r1;  wn[2] = ww[2] * r1;  wn[3] = ww[3] * r1;
    wn[4] = ww[4] * r2;  wn[5] = ww[5] * r2;  wn[6] = ww[6] * r2;
    wn[7] = ww[7] * r3;
}

__device__ __forceinline__ void site_compute(const float* vi, const float* wn,
                                             const float* wt, float* o) {
#pragma unroll
    for (int t = 0; t < 8; ++t) o[t] = 0.0f;
#define T(I, K, J, S, P) o[J] = fmaf((S) * wt[P] * vi[I], wn[K], o[J]);
    // i = 0 (scalar)
    T(0,0,0, 1.f, 0)  T(0,1,1, 1.f, 1)  T(0,2,2, 1.f, 1)  T(0,3,3, 1.f, 1)
    T(0,4,4, 1.f, 2)  T(0,5,5, 1.f, 2)  T(0,6,6, 1.f, 2)  T(0,7,7, 1.f, 3)
    // i = 1 (e1)
    T(1,0,1, 1.f, 5)  T(1,1,0, 1.f, 4)  T(1,2,4, 1.f, 7)  T(1,3,5, 1.f, 7)
    T(1,4,2, 1.f, 6)  T(1,5,3, 1.f, 6)  T(1,6,7, 1.f, 9)  T(1,7,6, 1.f, 8)
    // i = 2 (e2)
    T(2,0,2, 1.f, 5)  T(2,1,4,-1.f, 7)  T(2,2,0, 1.f, 4)  T(2,3,6, 1.f, 7)
    T(2,4,1,-1.f, 6)  T(2,5,7,-1.f, 9)  T(2,6,3, 1.f, 6)  T(2,7,5,-1.f, 8)
    // i = 3 (e3)
    T(3,0,3, 1.f, 5)  T(3,1,5,-1.f, 7)  T(3,2,6,-1.f, 7)  T(3,3,0, 1.f, 4)
    T(3,4,7, 1.f, 9)  T(3,5,1,-1.f, 6)  T(3,6,2,-1.f, 6)  T(3,7,4, 1.f, 8)
    // i = 4 (e12)
    T(4,0,4,-1.f,13)  T(4,1,2, 1.f,11)  T(4,2,1,-1.f,11)  T(4,3,7,-1.f,15)
    T(4,4,0, 1.f,10)  T(4,5,6, 1.f,14)  T(4,6,5,-1.f,14)  T(4,7,3, 1.f,12)
    // i = 5 (e13)
    T(5,0,5,-1.f,13)  T(5,1,3, 1.f,11)  T(5,2,7, 1.f,15)  T(5,3,1,-1.f,11)
    T(5,4,6,-1.f,14)  T(5,5,0, 1.f,10)  T(5,6,4, 1.f,14)  T(5,7,2,-1.f,12)
    // i = 6 (e23)
    T(6,0,6,-1.f,13)  T(6,1,7,-1.f,15)  T(6,2,3, 1.f,11)  T(6,3,2,-1.f,11)
    T(6,4,5, 1.f,14)  T(6,5,4,-1.f,14)  T(6,6,0, 1.f,10)  T(6,7,1, 1.f,12)
    // i = 7 (e123)
    T(7,0,7,-1.f,19)  T(7,1,6,-1.f,18)  T(7,2,5, 1.f,18)  T(7,3,4,-1.f,18)
    T(7,4,3, 1.f,17)  T(7,5,2,-1.f,17)  T(7,6,1, 1.f,17)  T(7,7,0, 1.f,16)
#undef T
}

__global__ __launch_bounds__(NR, 4) void mv_gp_kernel(
    const float* __restrict__ v,
    const float* __restrict__ w,
    const float* __restrict__ weight,
    const float* __restrict__ a,
    float* __restrict__ out,
    int B, int F, int GY)
{
    __shared__ float wt_s[NR * PADW];   // row-major, padded (gcd(21,32)=1)

    const int tid = threadIdx.x;
    const int n0  = blockIdx.x * NR;

    // ---- stage weight rows: coalesced float4 reads, scalar padded writes ----
    {
        const float4* wsrc = (const float4*)(weight + (size_t)n0 * 20);
#pragma unroll
        for (int it = 0; it < 5; ++it) {
            int i = tid + it * NR;          // 1280 float4 total
            float4 x = wsrc[i];
            int e = i * 4;
            int base = (e / 20) * PADW + (e % 20);
            wt_s[base + 0] = x.x;
            wt_s[base + 1] = x.y;
            wt_s[base + 2] = x.z;
            wt_s[base + 3] = x.w;
        }
    }

    const int n = n0 + tid;

    // sigmoid(a[n]) — once per thread, serves all sites
    const float4 a4 = *(const float4*)(a + (size_t)n * 4);
    const float s0 = __fdividef(1.0f, 1.0f + __expf(-a4.x));
    const float s1 = __fdividef(1.0f, 1.0f + __expf(-a4.y));
    const float s2 = __fdividef(1.0f, 1.0f + __expf(-a4.z));
    const float s3 = __fdividef(1.0f, 1.0f + __expf(-a4.w));

    __syncthreads();

    // per-thread weight row from smem (conflict-free: stride 21) — once per thread
    float wt[20];
    const float* wrow = &wt_s[tid * PADW];
#pragma unroll
    for (int p = 0; p < 20; ++p) wt[p] = wrow[p];

    // ---- persistent loop over b-pairs ----
    for (int bp = blockIdx.y; bp * 2 < B; bp += GY) {
        const int b0 = bp * 2;
        const size_t siteA = (size_t)b0 * F + n;
        const size_t siteB = (b0 + 1 < B) ? siteA + (size_t)F : siteA;

        const float4* vA4 = (const float4*)(v + siteA * 8);
        const float4* wA4 = (const float4*)(w + siteA * 8);
        const float4* vB4 = (const float4*)(v + siteB * 8);
        const float4* wB4 = (const float4*)(w + siteB * 8);

        float4 va0 = vA4[0], va1 = vA4[1];
        float4 wa0 = wA4[0], wa1 = wA4[1];
        float4 vb0 = vB4[0], vb1 = vB4[1];
        float4 wb0 = wB4[0], wb1 = wB4[1];

        // ---- site A ----
        {
            float vi[8] = {va0.x, va0.y, va0.z, va0.w, va1.x, va1.y, va1.z, va1.w};
            float ww[8] = {wa0.x, wa0.y, wa0.z, wa0.w, wa1.x, wa1.y, wa1.z, wa1.w};
            float wn[8], o[8];
            normalize8(ww, s0, s1, s2, s3, wn);
            site_compute(vi, wn, wt, o);
            float4* o4 = (float4*)(out + siteA * 8);
            o4[0] = make_float4(o[0], o[1], o[2], o[3]);
            o4[1] = make_float4(o[4], o[5], o[6], o[7]);
        }
        // ---- site B ----
        {
            float vi[8] = {vb0.x, vb0.y, vb0.z, vb0.w, vb1.x, vb1.y, vb1.z, vb1.w};
            float ww[8] = {wb0.x, wb0.y, wb0.z, wb0.w, wb1.x, wb1.y, wb1.z, wb1.w};
            float wn[8], o[8];
            normalize8(ww, s0, s1, s2, s3, wn);
            site_compute(vi, wn, wt, o);
            float4* o4 = (float4*)(out + siteB * 8);
            o4[0] = make_float4(o[0], o[1], o[2], o[3]);
            o4[1] = make_float4(o[4], o[5], o[6], o[7]);
        }
    }
}

extern "C" void kernel_launch(void* const* d_in, const int* in_sizes, int n_in,
                              void* d_out, int out_size) {
    const float* v      = (const float*)d_in[0];
    const float* w      = (const float*)d_in[1];
    const float* weight = (const float*)d_in[2];
    const float* a      = (const float*)d_in[3];
    float* out = (float*)d_out;

    int F     = in_sizes[3] / 4;        // a is [F, 4]
    int total = in_sizes[0] / 8;        // B * F
    int B     = total / F;

    int gx = F / NR;                    // 3
    int npairs = (B + 1) / 2;           // 512
    // ~one full wave: 148 SMs x 4 blocks / gx
    int gy = (148 * 4) / (gx > 0 ? gx : 1);
    if (gy > npairs) gy = npairs;
    if (gy < 1) gy = 1;

    dim3 grid(gx, gy);
    mv_gp_kernel<<<grid, NR>>>(v, w, weight, a, out, B, F, gy);
}

// round 11
// speedup vs baseline: 1.4967x; 1.0713x over previous
#include <cuda_runtime.h>

// MVGeometricProduct — software-pipelined persistent loop.
// R10 (15.4us): ~53% stall fraction; each b-pair iteration exposes a full DRAM
// round trip (no regs for overlap under the 4-block/64-reg cap).
// Now: __launch_bounds__(256,2) frees registers for a next-pair prefetch buffer
// (8 float4). Grid = (3, 98) = 294 blocks ≈ one wave at 2 blocks/SM; 5-6 pairs
// per block. Prefetch hides DRAM latency behind the ~500-cycle compute phase.

#define NR 256
#define PADW 21

__device__ __forceinline__ void normalize8(const float* ww,
                                           float s0, float s1, float s2, float s3,
                                           float* wn) {
    float nrm0 = fabsf(ww[0]);
    float nrm1 = __fsqrt_rn(ww[1]*ww[1] + ww[2]*ww[2] + ww[3]*ww[3]);
    float nrm2 = __fsqrt_rn(ww[4]*ww[4] + ww[5]*ww[5] + ww[6]*ww[6]);
    float nrm3 = fabsf(ww[7]);
    float r0 = __fdividef(1.0f, fmaf(s0, nrm0 - 1.0f, 1.0f));
    float r1 = __fdividef(1.0f, fmaf(s1, nrm1 - 1.0f, 1.0f));
    float r2 = __fdividef(1.0f, fmaf(s2, nrm2 - 1.0f, 1.0f));
    float r3 = __fdividef(1.0f, fmaf(s3, nrm3 - 1.0f, 1.0f));
    wn[0] = ww[0] * r0;
    wn[1] = ww[1] * r1;  wn[2] = ww[2] * r1;  wn[3] = ww[3] * r1;
    wn[4] = ww[4] * r2;  wn[5] = ww[5] * r2;  wn[6] = ww[6] * r2;
    wn[7] = ww[7] * r3;
}

__device__ __forceinline__ void site_compute(const float* vi, const float* wn,
                                             const float* wt, float* o) {
#pragma unroll
    for (int t = 0; t < 8; ++t) o[t] = 0.0f;
#define T(I, K, J, S, P) o[J] = fmaf((S) * wt[P] * vi[I], wn[K], o[J]);
    // i = 0 (scalar)
    T(0,0,0, 1.f, 0)  T(0,1,1, 1.f, 1)  T(0,2,2, 1.f, 1)  T(0,3,3, 1.f, 1)
    T(0,4,4, 1.f, 2)  T(0,5,5, 1.f, 2)  T(0,6,6, 1.f, 2)  T(0,7,7, 1.f, 3)
    // i = 1 (e1)
    T(1,0,1, 1.f, 5)  T(1,1,0, 1.f, 4)  T(1,2,4, 1.f, 7)  T(1,3,5, 1.f, 7)
    T(1,4,2, 1.f, 6)  T(1,5,3, 1.f, 6)  T(1,6,7, 1.f, 9)  T(1,7,6, 1.f, 8)
    // i = 2 (e2)
    T(2,0,2, 1.f, 5)  T(2,1,4,-1.f, 7)  T(2,2,0, 1.f, 4)  T(2,3,6, 1.f, 7)
    T(2,4,1,-1.f, 6)  T(2,5,7,-1.f, 9)  T(2,6,3, 1.f, 6)  T(2,7,5,-1.f, 8)
    // i = 3 (e3)
    T(3,0,3, 1.f, 5)  T(3,1,5,-1.f, 7)  T(3,2,6,-1.f, 7)  T(3,3,0, 1.f, 4)
    T(3,4,7, 1.f, 9)  T(3,5,1,-1.f, 6)  T(3,6,2,-1.f, 6)  T(3,7,4, 1.f, 8)
    // i = 4 (e12)
    T(4,0,4,-1.f,13)  T(4,1,2, 1.f,11)  T(4,2,1,-1.f,11)  T(4,3,7,-1.f,15)
    T(4,4,0, 1.f,10)  T(4,5,6, 1.f,14)  T(4,6,5,-1.f,14)  T(4,7,3, 1.f,12)
    // i = 5 (e13)
    T(5,0,5,-1.f,13)  T(5,1,3, 1.f,11)  T(5,2,7, 1.f,15)  T(5,3,1,-1.f,11)
    T(5,4,6,-1.f,14)  T(5,5,0, 1.f,10)  T(5,6,4, 1.f,14)  T(5,7,2,-1.f,12)
    // i = 6 (e23)
    T(6,0,6,-1.f,13)  T(6,1,7,-1.f,15)  T(6,2,3, 1.f,11)  T(6,3,2,-1.f,11)
    T(6,4,5, 1.f,14)  T(6,5,4,-1.f,14)  T(6,6,0, 1.f,10)  T(6,7,1, 1.f,12)
    // i = 7 (e123)
    T(7,0,7,-1.f,19)  T(7,1,6,-1.f,18)  T(7,2,5, 1.f,18)  T(7,3,4,-1.f,18)
    T(7,4,3, 1.f,17)  T(7,5,2,-1.f,17)  T(7,6,1, 1.f,17)  T(7,7,0, 1.f,16)
#undef T
}

__device__ __forceinline__ void do_pair(
    const float4& va0, const float4& va1, const float4& wa0, const float4& wa1,
    const float4& vb0, const float4& vb1, const float4& wb0, const float4& wb1,
    float s0, float s1, float s2, float s3, const float* wt,
    float* __restrict__ out, size_t siteA, size_t siteB)
{
    // site A
    {
        float vi[8] = {va0.x, va0.y, va0.z, va0.w, va1.x, va1.y, va1.z, va1.w};
        float ww[8] = {wa0.x, wa0.y, wa0.z, wa0.w, wa1.x, wa1.y, wa1.z, wa1.w};
        float wn[8], o[8];
        normalize8(ww, s0, s1, s2, s3, wn);
        site_compute(vi, wn, wt, o);
        float4* o4 = (float4*)(out + siteA * 8);
        o4[0] = make_float4(o[0], o[1], o[2], o[3]);
        o4[1] = make_float4(o[4], o[5], o[6], o[7]);
    }
    // site B
    {
        float vi[8] = {vb0.x, vb0.y, vb0.z, vb0.w, vb1.x, vb1.y, vb1.z, vb1.w};
        float ww[8] = {wb0.x, wb0.y, wb0.z, wb0.w, wb1.x, wb1.y, wb1.z, wb1.w};
        float wn[8], o[8];
        normalize8(ww, s0, s1, s2, s3, wn);
        site_compute(vi, wn, wt, o);
        float4* o4 = (float4*)(out + siteB * 8);
        o4[0] = make_float4(o[0], o[1], o[2], o[3]);
        o4[1] = make_float4(o[4], o[5], o[6], o[7]);
    }
}

__global__ __launch_bounds__(NR, 2) void mv_gp_kernel(
    const float* __restrict__ v,
    const float* __restrict__ w,
    const float* __restrict__ weight,
    const float* __restrict__ a,
    float* __restrict__ out,
    int B, int F, int GY)
{
    __shared__ float wt_s[NR * PADW];   // row-major, padded (gcd(21,32)=1)

    const int tid = threadIdx.x;
    const int n0  = blockIdx.x * NR;

    // ---- stage weight rows: coalesced float4 reads, scalar padded writes ----
    {
        const float4* wsrc = (const float4*)(weight + (size_t)n0 * 20);
#pragma unroll
        for (int it = 0; it < 5; ++it) {
            int i = tid + it * NR;          // 1280 float4 total
            float4 x = wsrc[i];
            int e = i * 4;
            int base = (e / 20) * PADW + (e % 20);
            wt_s[base + 0] = x.x;
            wt_s[base + 1] = x.y;
            wt_s[base + 2] = x.z;
            wt_s[base + 3] = x.w;
        }
    }

    const int n = n0 + tid;

    // sigmoid(a[n]) — once per thread
    const float4 a4 = *(const float4*)(a + (size_t)n * 4);
    const float s0 = __fdividef(1.0f, 1.0f + __expf(-a4.x));
    const float s1 = __fdividef(1.0f, 1.0f + __expf(-a4.y));
    const float s2 = __fdividef(1.0f, 1.0f + __expf(-a4.z));
    const float s3 = __fdividef(1.0f, 1.0f + __expf(-a4.w));

    __syncthreads();

    // per-thread weight row (conflict-free: stride 21) — once per thread
    float wt[20];
    const float* wrow = &wt_s[tid * PADW];
#pragma unroll
    for (int p = 0; p < 20; ++p) wt[p] = wrow[p];

    const int npairs = (B + 1) / 2;

    int bp = blockIdx.y;
    if (bp >= npairs) return;

    size_t siteA = (size_t)(bp * 2) * F + n;
    size_t siteB = siteA + (size_t)F;    // B even in this workload

    // ---- prologue: load first pair ----
    const float4* pvA = (const float4*)(v + siteA * 8);
    const float4* pwA = (const float4*)(w + siteA * 8);
    const float4* pvB = (const float4*)(v + siteB * 8);
    const float4* pwB = (const float4*)(w + siteB * 8);
    float4 cva0 = pvA[0], cva1 = pvA[1];
    float4 cwa0 = pwA[0], cwa1 = pwA[1];
    float4 cvb0 = pvB[0], cvb1 = pvB[1];
    float4 cwb0 = pwB[0], cwb1 = pwB[1];

    // ---- pipelined loop ----
    for (;;) {
        const int nbp = bp + GY;
        const bool more = (nbp < npairs);

        float4 nva0, nva1, nwa0, nwa1, nvb0, nvb1, nwb0, nwb1;
        size_t nsiteA = siteA, nsiteB = siteB;
        if (more) {
            nsiteA = (size_t)(nbp * 2) * F + n;
            nsiteB = nsiteA + (size_t)F;
            const float4* qvA = (const float4*)(v + nsiteA * 8);
            const float4* qwA = (const float4*)(w + nsiteA * 8);
            const float4* qvB = (const float4*)(v + nsiteB * 8);
            const float4* qwB = (const float4*)(w + nsiteB * 8);
            nva0 = qvA[0]; nva1 = qvA[1];
            nwa0 = qwA[0]; nwa1 = qwA[1];
            nvb0 = qvB[0]; nvb1 = qvB[1];
            nwb0 = qwB[0]; nwb1 = qwB[1];
        }

        do_pair(cva0, cva1, cwa0, cwa1, cvb0, cvb1, cwb0, cwb1,
                s0, s1, s2, s3, wt, out, siteA, siteB);

        if (!more) break;

        bp = nbp; siteA = nsiteA; siteB = nsiteB;
        cva0 = nva0; cva1 = nva1; cwa0 = nwa0; cwa1 = nwa1;
        cvb0 = nvb0; cvb1 = nvb1; cwb0 = nwb0; cwb1 = nwb1;
    }
}

extern "C" void kernel_launch(void* const* d_in, const int* in_sizes, int n_in,
                              void* d_out, int out_size) {
    const float* v      = (const float*)d_in[0];
    const float* w      = (const float*)d_in[1];
    const float* weight = (const float*)d_in[2];
    const float* a      = (const float*)d_in[3];
    float* out = (float*)d_out;

    int F     = in_sizes[3] / 4;        // a is [F, 4]
    int total = in_sizes[0] / 8;        // B * F
    int B     = total / F;

    int gx = F / NR;                    // 3
    int npairs = (B + 1) / 2;           // 512
    // one wave at 2 blocks/SM: 148*2 / gx
    int gy = (148 * 2) / (gx > 0 ? gx : 1);
    if (gy > npairs) gy = npairs;
    if (gy < 1) gy = 1;

    dim3 grid(gx, gy);
    mv_gp_kernel<<<grid, NR>>>(v, w, weight, a, out, B, F, gy);
}